// round 5
// baseline (speedup 1.0000x reference)
#include <cuda_runtime.h>
#include <cstdint>

#define NIMG   32
#define CINCH  256
#define COUTCH 256
#define HIMG   56
#define WIMG   56
#define HWSZ   (HIMG*WIMG)           // 3136
#define PDIM   58
#define IMG_PIX (PDIM*PDIM)          // 3364
#define PIX    (NIMG*IMG_PIX)        // 107648 = 841*128
#define GUARD  64
#define TOT_ROWS (GUARD + PIX + GUARD)
#define XROW   512                   // bytes per X_t row: [a1:256 | a2:256]
#define AROW   2304                  // bytes per weight row (9*256)
#define NTILES 841                   // PIX / 128

#define BM 128
#define BN 128
#define NITER 36                     // 9 taps * 4 chunks of 64
#define SROW 80                      // padded smem row stride (conflict-free)
#define ST_A  0
#define ST_B1 (128*SROW)             // 10240
#define ST_B2 (2*128*SROW)           // 20480
#define STAGE_BYTES (3*128*SROW)     // 30720
#define SMEM_TOTAL (3*STAGE_BYTES)   // 92160

__device__ __align__(256) char g_xt8[(size_t)TOT_ROWS * XROW];   // ~55.4 MB
__device__ __align__(256) char g_aw8[(size_t)COUTCH * AROW];     // ~590 KB

// ---------------- Kernel 1: weight prep (int32 ternary -> int8, [co][tap*256+ci]) ----------------
__global__ void prep_w_kernel(const int* __restrict__ wq) {
    int t = blockIdx.x * 256 + threadIdx.x;
    if (t >= 9 * 256 * 256) return;
    int ci = t & 255, co = (t >> 8) & 255, tap = t >> 16;
    g_aw8[(size_t)co * AROW + tap * 256 + ci] = (char)wq[(co * 256 + ci) * 9 + tap];
}

// ---------------- Kernel 2: zero guards + padded-border rows of X_t ----------------
__global__ void zero_xt_kernel() {
    const int NROWS = 128 + NIMG * 228;      // 7424
    long long t = (long long)blockIdx.x * blockDim.x + threadIdx.x;
    if (t >= (long long)NROWS * 32) return;  // 32 uint4 per row
    int r = (int)(t >> 5), c = (int)(t & 31);
    size_t row;
    if (r < 64) row = (size_t)r;                               // front guard
    else if (r < 128) row = (size_t)GUARD + PIX + (r - 64);    // back guard
    else {
        int rb = r - 128, n = rb / 228, b = rb % 228;
        int ph, pw;
        if (b < 58)        { ph = 0;           pw = b; }
        else if (b < 116)  { ph = 57;          pw = b - 58; }
        else if (b < 172)  { ph = b - 116 + 1; pw = 0; }
        else               { ph = b - 172 + 1; pw = 57; }
        row = (size_t)GUARD + (size_t)n * IMG_PIX + (size_t)ph * PDIM + pw;
    }
    ((uint4*)g_xt8)[row * 32 + c] = make_uint4(0, 0, 0, 0);
}

// ---------------- Kernel 3: activation prep (clamp + 2-level int8 + transpose) ----------------
__global__ void __launch_bounds__(256) prep_x_kernel(const float* __restrict__ x) {
    __shared__ char sp[56 * 516];
    int nh = blockIdx.x;
    int n = nh / HIMG, h = nh % HIMG;
    int tid = threadIdx.x;
    const float c1f = 1.0f / 127.0f;
    for (int idx = tid; idx < 256 * WIMG; idx += 256) {
        int ci = idx / WIMG, w = idx - ci * WIMG;
        float v = x[(((size_t)n * CINCH + ci) * HIMG + h) * WIMG + w];
        v = fminf(fmaxf(v, -1.0f), 1.0f);
        int a1 = __float2int_rn(v * 127.0f);
        float r = fmaf((float)a1, -c1f, v);
        int a2 = __float2int_rn(r * 32258.0f);
        a2 = max(-127, min(127, a2));
        sp[w * 516 + ci]       = (char)a1;
        sp[w * 516 + 256 + ci] = (char)a2;
    }
    __syncthreads();
    size_t rowbase = (size_t)GUARD + (size_t)n * IMG_PIX + (size_t)(h + 1) * PDIM + 1;
    for (int g = tid; g < 56 * 128; g += 256) {
        int w = g >> 7, wi = g & 127;
        uint32_t val = *(const uint32_t*)(sp + w * 516 + wi * 4);
        *(uint32_t*)(g_xt8 + (rowbase + w) * XROW + wi * 4) = val;
    }
}

// ---------------- Kernel 4: int8 implicit-GEMM conv ----------------
__device__ __forceinline__ void mma_s8(int* c, const uint32_t* a, const uint32_t* b) {
    asm volatile(
        "mma.sync.aligned.m16n8k32.row.col.s32.s8.s8.s32 "
        "{%0,%1,%2,%3}, {%4,%5,%6,%7}, {%8,%9}, {%0,%1,%2,%3};"
        : "+r"(c[0]), "+r"(c[1]), "+r"(c[2]), "+r"(c[3])
        : "r"(a[0]), "r"(a[1]), "r"(a[2]), "r"(a[3]), "r"(b[0]), "r"(b[1]));
}
__device__ __forceinline__ void cp16(uint32_t dst, const void* src) {
    asm volatile("cp.async.cg.shared.global [%0], [%1], 16;" :: "r"(dst), "l"(src));
}

__global__ void __launch_bounds__(256, 1)
gemm_kernel(const float* __restrict__ s, const float* __restrict__ bias,
            float* __restrict__ out)
{
    extern __shared__ char sm[];
    uint32_t smb = (uint32_t)__cvta_generic_to_shared(sm);
    int tid = threadIdx.x, lane = tid & 31, wid = tid >> 5;
    int quad = lane >> 2, tq = lane & 3;
    int warp_m = wid & 3, warp_n = wid >> 2;       // 4 x 2 warps: 32x64 warp tiles
    int p0 = blockIdx.x * BN;
    int co0 = blockIdx.y * BM;

    int acc1[2][8][4], acc2[2][8][4];
    #pragma unroll
    for (int mi = 0; mi < 2; mi++)
        #pragma unroll
        for (int ni = 0; ni < 8; ni++)
            #pragma unroll
            for (int r = 0; r < 4; r++) { acc1[mi][ni][r] = 0; acc2[mi][ni][r] = 0; }

    // ---- cp.async stage loader: 6 x 16B per thread ----
    auto issue = [&](int it, int st) {
        int tap = it >> 2, kc = it & 3;
        int kh = tap / 3, kw = tap - kh * 3;
        int tapoff = (kh - 1) * PDIM + (kw - 1);       // computed inline
        const char* asrc = g_aw8 + (size_t)co0 * AROW + tap * 256 + kc * 64;
        const char* bsrc = g_xt8 + ((size_t)(GUARD + p0 + tapoff)) * XROW + kc * 64;
        uint32_t sbase = smb + st * STAGE_BYTES;
        #pragma unroll
        for (int i = 0; i < 6; i++) {
            int g = tid + i * 256;
            int row = (g & 511) >> 2, ch = g & 3;
            if (g < 512)
                cp16(sbase + ST_A + row * SROW + ch * 16, asrc + (size_t)row * AROW + ch * 16);
            else if (g < 1024)
                cp16(sbase + ST_B1 + row * SROW + ch * 16, bsrc + (size_t)row * XROW + ch * 16);
            else
                cp16(sbase + ST_B2 + row * SROW + ch * 16, bsrc + 256 + (size_t)row * XROW + ch * 16);
        }
    };

    issue(0, 0); asm volatile("cp.async.commit_group;" ::: "memory");
    issue(1, 1); asm volatile("cp.async.commit_group;" ::: "memory");

    for (int it = 0; it < NITER; it++) {
        asm volatile("cp.async.wait_group 1;" ::: "memory");
        __syncthreads();
        if (it + 2 < NITER) issue(it + 2, (it + 2) % 3);
        asm volatile("cp.async.commit_group;" ::: "memory");

        char* st = sm + (it % 3) * STAGE_BYTES;
        const char* sA = st + ST_A + warp_m * 32 * SROW;
        const char* sB1 = st + ST_B1 + warp_n * 64 * SROW;
        const char* sB2 = st + ST_B2 + warp_n * 64 * SROW;

        #pragma unroll
        for (int ks = 0; ks < 2; ks++) {
            int col = ks * 32 + tq * 4;
            uint32_t a[2][4];
            #pragma unroll
            for (int mi = 0; mi < 2; mi++) {
                int r0 = mi * 16 + quad;
                a[mi][0] = *(const uint32_t*)(sA + r0 * SROW + col);
                a[mi][1] = *(const uint32_t*)(sA + (r0 + 8) * SROW + col);
                a[mi][2] = *(const uint32_t*)(sA + r0 * SROW + col + 16);
                a[mi][3] = *(const uint32_t*)(sA + (r0 + 8) * SROW + col + 16);
            }
            {
                uint32_t b[8][2];
                #pragma unroll
                for (int ni = 0; ni < 8; ni++) {
                    int n0 = ni * 8 + quad;
                    b[ni][0] = *(const uint32_t*)(sB1 + n0 * SROW + col);
                    b[ni][1] = *(const uint32_t*)(sB1 + n0 * SROW + col + 16);
                }
                #pragma unroll
                for (int mi = 0; mi < 2; mi++)
                    #pragma unroll
                    for (int ni = 0; ni < 8; ni++)
                        mma_s8(acc1[mi][ni], a[mi], b[ni]);
            }
            {
                uint32_t b[8][2];
                #pragma unroll
                for (int ni = 0; ni < 8; ni++) {
                    int n0 = ni * 8 + quad;
                    b[ni][0] = *(const uint32_t*)(sB2 + n0 * SROW + col);
                    b[ni][1] = *(const uint32_t*)(sB2 + n0 * SROW + col + 16);
                }
                #pragma unroll
                for (int mi = 0; mi < 2; mi++)
                    #pragma unroll
                    for (int ni = 0; ni < 8; ni++)
                        mma_s8(acc2[mi][ni], a[mi], b[ni]);
            }
        }
    }

    // ---- epilogue: combine planes, scale+bias, scatter to NCHW ----
    const float c1f = 1.0f / 127.0f;
    const float c2f = 1.0f / 32258.0f;
    #pragma unroll
    for (int mi = 0; mi < 2; mi++) {
        #pragma unroll
        for (int half = 0; half < 2; half++) {
            int co = co0 + warp_m * 32 + mi * 16 + half * 8 + quad;
            float sv = s[co], bv = bias[co];
            #pragma unroll
            for (int ni = 0; ni < 8; ni++) {
                #pragma unroll
                for (int e = 0; e < 2; e++) {
                    int ridx = half * 2 + e;
                    float f = (float)acc1[mi][ni][ridx] * c1f
                            + (float)acc2[mi][ni][ridx] * c2f;
                    float y = fmaf(f, sv, bv);
                    int q = p0 + warp_n * 64 + ni * 8 + tq * 2 + e;
                    int n = q / IMG_PIX;
                    int rem = q - n * IMG_PIX;
                    int ph = rem / PDIM, pw = rem - ph * PDIM;
                    if ((unsigned)(ph - 1) < HIMG && (unsigned)(pw - 1) < WIMG)
                        out[((size_t)n * COUTCH + co) * HWSZ + (ph - 1) * WIMG + (pw - 1)] = y;
                }
            }
        }
    }
}

// ---------------- Host ----------------
extern "C" void kernel_launch(void* const* d_in, const int* in_sizes, int n_in,
                              void* d_out, int out_size) {
    const float* x    = (const float*)d_in[0];
    const int*   wq   = (const int*)d_in[1];
    const float* s    = (const float*)d_in[2];
    const float* bias = (const float*)d_in[3];
    float* out = (float*)d_out;

    cudaFuncSetAttribute(gemm_kernel, cudaFuncAttributeMaxDynamicSharedMemorySize, SMEM_TOTAL);

    prep_w_kernel<<<(9 * 256 * 256 + 255) / 256, 256>>>(wq);
    {
        const long long zt = (long long)(128 + NIMG * 228) * 32;
        zero_xt_kernel<<<(int)((zt + 255) / 256), 256>>>();
    }
    prep_x_kernel<<<NIMG * HIMG, 256>>>(x);
    gemm_kernel<<<dim3(NTILES, 2), 256, SMEM_TOTAL>>>(s, bias, out);
}